// round 15
// baseline (speedup 1.0000x reference)
#include <cuda_runtime.h>
#include <cuda_fp16.h>
#include <cstdint>

// EdgeNetwork via single-piece fp16 mma.sync m16n8k16.
// H = E@W + b ; messages[g,i] = sum_j relu(H[g, 32i+j]) * s[g,j]
// E, W rounded to fp16 (rel err ~3e-4 << 1e-3); accum + epilogue fp32.
// R15: packed f32x2 epilogue accumulation + s-layout [row][q][a][sel] so each
// thread's s comes as 2x LDS.128 pre-packed for fma.rn.f32x2.

#define NTHREADS 256
typedef unsigned long long u64;

// dynamic smem offsets (bytes)
#define SM_EH   0                        // uint2[512]           4 KB
#define SM_SP   4096                     // float[4096]         16 KB
#define SM_OSM  20480                    // float[128*68]    34816 B
#define SM_TOTAL (20480 + 34816)         // 55296 B/CTA (x3 = 162 KB/SM)

// fp16 W, fragment-permuted:
// d_Wh[n*4+q] = { h2(w[2q][n],w[2q+1][n]), h2(w[2q+8][n],w[2q+9][n]) }
__device__ uint2 d_Wh[4096];

__device__ __forceinline__ uint32_t pack_h2f(float a, float b) {
    __half2 h = __floats2half2_rn(a, b);
    return *reinterpret_cast<uint32_t*>(&h);
}
__device__ __forceinline__ void fma2(u64& acc, u64 a, u64 b) {
    asm("fma.rn.f32x2 %0, %1, %2, %0;" : "+l"(acc) : "l"(a), "l"(b));
}

__global__ void prep_w(const float* __restrict__ W) {
    int idx = blockIdx.x * 256 + threadIdx.x;   // 0..4095 over [n][q]
    int n = idx >> 2, q = idx & 3;
    d_Wh[idx] = make_uint2(
        pack_h2f(W[(2 * q)     * 1024 + n], W[(2 * q + 1) * 1024 + n]),
        pack_h2f(W[(2 * q + 8) * 1024 + n], W[(2 * q + 9) * 1024 + n]));
}

// D = A*B + {cx,cy,cx,cy}
__device__ __forceinline__ void mma16c(float* d, uint32_t a0, uint32_t a1,
                                       uint32_t a2, uint32_t a3,
                                       uint32_t b0, uint32_t b1,
                                       float cx, float cy) {
    asm volatile(
        "mma.sync.aligned.m16n8k16.row.col.f32.f16.f16.f32 "
        "{%0,%1,%2,%3}, {%4,%5,%6,%7}, {%8,%9}, {%10,%11,%10,%11};"
        : "=f"(d[0]), "=f"(d[1]), "=f"(d[2]), "=f"(d[3])
        : "r"(a0), "r"(a1), "r"(a2), "r"(a3), "r"(b0), "r"(b1),
          "f"(cx), "f"(cy));
}

__global__ __launch_bounds__(NTHREADS, 3) void edge_net_mma(
    const float* __restrict__ states,
    const float* __restrict__ edges,
    const float* __restrict__ bg,
    float* __restrict__ out)
{
    extern __shared__ char sm[];
    uint2* EH  = (uint2*)(sm + SM_EH);       // [row][q]
    float* SPN = (float*)(sm + SM_SP);       // [row][q][a][sel] : row*32+q*8+a*2+sel
    float* OSM = (float*)(sm + SM_OSM);      // [row][il][q], pitch 68

    const int tid = threadIdx.x;
    const int eb = blockIdx.x & 511;         // edge block (128 edges)
    const int cb = blockIdx.x >> 9;          // column half (512 cols)
    const int gbase = eb * 128;
    const int col0 = cb * 512;

    const int w = tid >> 5, lane = tid & 31;
    const int g = lane >> 2;                 // groupID: row-in-tile / B-col
    const int q = lane & 3;                  // threadID-in-group

    // ---- Stage edges as fp16 fragments ----
    {
        const float2* er = (const float2*)(edges + (size_t)gbase * 16);
        #pragma unroll
        for (int k = 0; k < 2; k++) {
            int item = tid + k * 256;        // 0..511 over [row][q]
            int row = item >> 2, qq = item & 3;
            float2 v0 = er[row * 8 + qq];
            float2 v1 = er[row * 8 + qq + 4];
            EH[item] = make_uint2(pack_h2f(v0.x, v0.y), pack_h2f(v1.x, v1.y));
        }
    }
    // ---- Stage states: SPN[row*32 + q*8 + a*2 + sel] = s[row][8a+2q+sel] ----
    {
        const float4* sv = (const float4*)(states + (size_t)gbase * 32);
        #pragma unroll
        for (int k = 0; k < 4; k++) {
            int idx = tid + k * 256;         // 0..1023 over [row][f4]
            int row = idx >> 3, f4 = idx & 7;
            float4 v = sv[idx];
            int base = row * 32 + (f4 & 1) * 16 + (f4 >> 1) * 2;
            *(float2*)(SPN + base)     = make_float2(v.x, v.y);
            *(float2*)(SPN + base + 8) = make_float2(v.z, v.w);
        }
    }
    __syncthreads();

    // ---- W + bias fragments -> registers (after sync) ----
    uint2 wh[8];
    float2 b2[8];
    #pragma unroll
    for (int ct = 0; ct < 8; ct++) {
        int n = col0 + w * 64 + ct * 8 + g;
        wh[ct] = d_Wh[n * 4 + q];
        b2[ct] = *(const float2*)(bg + col0 + w * 64 + ct * 8 + 2 * q);
    }

    // ---- Main: 8 rolled steps of 16 rows ----
    #pragma unroll 1
    for (int hp = 0; hp < 8; hp++) {
        const int rb = hp * 16;

        const uint2 aA = EH[(rb + g) * 4 + q];        // rows g
        const uint2 aB = EH[(rb + 8 + g) * 4 + q];    // rows g+8

        // s for this thread, both rows, all 4 a-groups (pre-packed pairs)
        const float* sp0 = SPN + (rb + g) * 32 + q * 8;
        const float* sp1 = SPN + (rb + 8 + g) * 32 + q * 8;
        float4 s0lo = *(const float4*)(sp0);          // a=0,1 pairs
        float4 s0hi = *(const float4*)(sp0 + 4);      // a=2,3 pairs
        float4 s1lo = *(const float4*)(sp1);
        float4 s1hi = *(const float4*)(sp1 + 4);
        const ulonglong2* s0l = (const ulonglong2*)&s0lo;
        const ulonglong2* s0h = (const ulonglong2*)&s0hi;
        const ulonglong2* s1l = (const ulonglong2*)&s1lo;
        const ulonglong2* s1h = (const ulonglong2*)&s1hi;
        u64 sA[4] = { s0l->x, s0l->y, s0h->x, s0h->y };   // row g, a=0..3
        u64 sB[4] = { s1l->x, s1l->y, s1h->x, s1h->y };   // row g+8

        u64 mm01[2] = {0ull, 0ull};          // [ip] packed acc, row g
        u64 mm23[2] = {0ull, 0ull};          // [ip] packed acc, row g+8

        #pragma unroll
        for (int a = 0; a < 4; a++) {
            #pragma unroll
            for (int ip = 0; ip < 2; ip++) {
                const int ct = ip * 4 + a;
                float d[4];
                mma16c(d, aA.x, aB.x, aA.y, aB.y, wh[ct].x, wh[ct].y,
                       b2[ct].x, b2[ct].y);

                float2 r01, r23;
                r01.x = fmaxf(d[0], 0.f);  r01.y = fmaxf(d[1], 0.f);
                r23.x = fmaxf(d[2], 0.f);  r23.y = fmaxf(d[3], 0.f);
                fma2(mm01[ip], *(u64*)&r01, sA[a]);
                fma2(mm23[ip], *(u64*)&r23, sB[a]);
            }
        }

        // ---- Unpack-add, store quad partials (conflict-free: bank = 4g+q) ----
        #pragma unroll
        for (int ip = 0; ip < 2; ip++) {
            const int il = w * 2 + ip;       // local column 0..15
            float2 m01 = *(float2*)&mm01[ip];
            float2 m23 = *(float2*)&mm23[ip];
            OSM[(rb + g) * 68 + il * 4 + q]     = m01.x + m01.y;
            OSM[(rb + 8 + g) * 68 + il * 4 + q] = m23.x + m23.y;
        }
    }

    // ---- Flush: sum 4 partials per output, coalesced STG ----
    __syncthreads();
    #pragma unroll
    for (int k = 0; k < 8; k++) {
        int idx = tid + k * 256;             // 0..2047 over [row][il]
        int row = idx >> 4, il = idx & 15;
        float4 p = *(const float4*)(OSM + row * 68 + il * 4);
        out[(size_t)(gbase + row) * 32 + cb * 16 + il] =
            (p.x + p.y) + (p.z + p.w);
    }
}

extern "C" void kernel_launch(void* const* d_in, const int* in_sizes, int n_in,
                              void* d_out, int out_size)
{
    const float* states = (const float*)d_in[0];  // [16, 4096, 32]
    const float* edges  = (const float*)d_in[1];  // [16, 4096, 16]
    const float* W      = (const float*)d_in[2];  // [16, 1024]
    const float* b      = (const float*)d_in[3];  // [1024]
    float* out          = (float*)d_out;          // [16, 4096, 32]

    (void)in_sizes; (void)n_in; (void)out_size;

    static int configured = 0;
    if (!configured) {
        cudaFuncSetAttribute(edge_net_mma,
                             cudaFuncAttributeMaxDynamicSharedMemorySize, SM_TOTAL);
        configured = 1;
    }
    prep_w<<<16, 256>>>(W);
    edge_net_mma<<<1024, NTHREADS, SM_TOTAL>>>(states, edges, b, out);
}